// round 12
// baseline (speedup 1.0000x reference)
#include <cuda_runtime.h>
#include <cuda_fp16.h>
#include <math_constants.h>

#define NN 50000
#define EE 800000
#define DD 128
#define NEG_SLOPE 0.2f
#define HS 136          // smem half-stride (conflict-free for quad fragment loads)

// ---------------- device scratch (static, no allocation) ----------------
__device__ __half g_hh[(size_t)NN * DD]; // transformed features (fp16)
__device__ float g_as[NN];
__device__ float g_ad[NN];
__device__ int   g_deg[NN];
__device__ int   g_off[NN + 1];
__device__ int   g_cur[NN];
__device__ int   g_ssrc[EE];             // edge src sorted by dst (fork stream)

// ---------------- 1) HMMA GEMM: h = x @ W (fp16 in, fp32 acc) ----------------
// 128x128x128 tile, 256 thr = 8 warps (4 m-warps x 2 n-warps).
// W converted fp32->fp16 transposed inline. Fused a_s/a_d epilogue from fp32
// accumulators; h stored fp16 via smem staging.
__global__ void gat_gemm_hmma(const float* __restrict__ x,
                              const float* __restrict__ W,
                              const float* __restrict__ att_s,
                              const float* __restrict__ att_d)
{
    extern __shared__ char smbuf[];
    __half* As = (__half*)smbuf;                 // [128][HS]
    __half* Bs = As + 128 * HS;                  // [128][HS] (n-major: Bs[n][k])
    float*  s_as = (float*)(Bs + 128 * HS);      // [128]
    float*  s_ad = s_as + 128;                   // [128]

    const int tid  = threadIdx.x;
    const int wid  = tid >> 5;
    const int lane = tid & 31;
    const int g    = lane >> 2;                  // group id (0..7)
    const int tg   = lane & 3;                   // thread-in-group
    const int m0   = blockIdx.x * 128;
    const int warp_m = wid & 3;                  // 0..3 (32 rows each)
    const int warp_n = wid >> 2;                 // 0..1 (64 cols each)

    if (tid < 128) { s_as[tid] = 0.f; s_ad[tid] = 0.f; }

    // load x tile fp32 -> fp16 into As (zero-pad OOB rows)
    #pragma unroll
    for (int t = 0; t < 16; t++) {
        int idx = tid + 256 * t;                 // float4 id over [128][32]
        int r = idx >> 5, c4 = idx & 31;
        float4 v = make_float4(0.f, 0.f, 0.f, 0.f);
        int row = m0 + r;
        if (row < NN) v = ((const float4*)x)[(size_t)row * 32 + c4];
        __half2 h0 = __floats2half2_rn(v.x, v.y);
        __half2 h1 = __floats2half2_rn(v.z, v.w);
        uint2 pk;
        pk.x = *(const unsigned int*)&h0;
        pk.y = *(const unsigned int*)&h1;
        *(uint2*)&As[r * HS + c4 * 4] = pk;
    }
    // load W fp32 -> fp16 TRANSPOSED into Bs: Bs[n][k] = W[k][n]
    #pragma unroll
    for (int t = 0; t < 16; t++) {
        int idx = tid + 256 * t;                 // float4 id over [128 k][32 n4]
        int k = idx >> 5, n4 = idx & 31;
        float4 v = ((const float4*)W)[idx];
        Bs[(n4 * 4 + 0) * HS + k] = __float2half(v.x);
        Bs[(n4 * 4 + 1) * HS + k] = __float2half(v.y);
        Bs[(n4 * 4 + 2) * HS + k] = __float2half(v.z);
        Bs[(n4 * 4 + 3) * HS + k] = __float2half(v.w);
    }
    __syncthreads();

    float acc[2][8][4];
    #pragma unroll
    for (int mi = 0; mi < 2; mi++)
        #pragma unroll
        for (int ni = 0; ni < 8; ni++)
            #pragma unroll
            for (int q = 0; q < 4; q++) acc[mi][ni][q] = 0.f;

    #pragma unroll
    for (int ks = 0; ks < 8; ks++) {
        const int k0 = ks * 16;
        unsigned int a[2][4];
        #pragma unroll
        for (int mi = 0; mi < 2; mi++) {
            int r = warp_m * 32 + mi * 16;
            a[mi][0] = *(const unsigned int*)&As[(r + g)     * HS + k0 +     tg * 2];
            a[mi][1] = *(const unsigned int*)&As[(r + g + 8) * HS + k0 +     tg * 2];
            a[mi][2] = *(const unsigned int*)&As[(r + g)     * HS + k0 + 8 + tg * 2];
            a[mi][3] = *(const unsigned int*)&As[(r + g + 8) * HS + k0 + 8 + tg * 2];
        }
        #pragma unroll
        for (int ni = 0; ni < 8; ni++) {
            int n = warp_n * 64 + ni * 8 + g;
            unsigned int b0 = *(const unsigned int*)&Bs[n * HS + k0 +     tg * 2];
            unsigned int b1 = *(const unsigned int*)&Bs[n * HS + k0 + 8 + tg * 2];
            #pragma unroll
            for (int mi = 0; mi < 2; mi++) {
                asm volatile(
                    "mma.sync.aligned.m16n8k16.row.col.f32.f16.f16.f32 "
                    "{%0,%1,%2,%3}, {%4,%5,%6,%7}, {%8,%9}, {%0,%1,%2,%3};"
                    : "+f"(acc[mi][ni][0]), "+f"(acc[mi][ni][1]),
                      "+f"(acc[mi][ni][2]), "+f"(acc[mi][ni][3])
                    : "r"(a[mi][0]), "r"(a[mi][1]), "r"(a[mi][2]), "r"(a[mi][3]),
                      "r"(b0), "r"(b1));
            }
        }
    }

    // ---- a_s / a_d partial dots from fp32 accumulators ----
    float ps[2][2] = {{0.f,0.f},{0.f,0.f}};
    float pd[2][2] = {{0.f,0.f},{0.f,0.f}};
    #pragma unroll
    for (int ni = 0; ni < 8; ni++) {
        int n = warp_n * 64 + ni * 8 + tg * 2;
        float sa0 = att_s[n], sa1 = att_s[n + 1];
        float da0 = att_d[n], da1 = att_d[n + 1];
        #pragma unroll
        for (int mi = 0; mi < 2; mi++) {
            ps[mi][0] = fmaf(acc[mi][ni][0], sa0, fmaf(acc[mi][ni][1], sa1, ps[mi][0]));
            ps[mi][1] = fmaf(acc[mi][ni][2], sa0, fmaf(acc[mi][ni][3], sa1, ps[mi][1]));
            pd[mi][0] = fmaf(acc[mi][ni][0], da0, fmaf(acc[mi][ni][1], da1, pd[mi][0]));
            pd[mi][1] = fmaf(acc[mi][ni][2], da0, fmaf(acc[mi][ni][3], da1, pd[mi][1]));
        }
    }
    #pragma unroll
    for (int sh = 1; sh <= 2; sh <<= 1) {
        #pragma unroll
        for (int mi = 0; mi < 2; mi++) {
            ps[mi][0] += __shfl_xor_sync(0xffffffffu, ps[mi][0], sh);
            ps[mi][1] += __shfl_xor_sync(0xffffffffu, ps[mi][1], sh);
            pd[mi][0] += __shfl_xor_sync(0xffffffffu, pd[mi][0], sh);
            pd[mi][1] += __shfl_xor_sync(0xffffffffu, pd[mi][1], sh);
        }
    }
    if (tg == 0) {
        #pragma unroll
        for (int mi = 0; mi < 2; mi++) {
            int r = warp_m * 32 + mi * 16 + g;
            atomicAdd(&s_as[r],     ps[mi][0]);
            atomicAdd(&s_as[r + 8], ps[mi][1]);
            atomicAdd(&s_ad[r],     pd[mi][0]);
            atomicAdd(&s_ad[r + 8], pd[mi][1]);
        }
    }

    // ---- stage h (fp16) into As, then coalesced store ----
    __syncthreads();          // all warps done reading As/Bs
    #pragma unroll
    for (int mi = 0; mi < 2; mi++) {
        #pragma unroll
        for (int ni = 0; ni < 8; ni++) {
            int r0 = warp_m * 32 + mi * 16 + g;
            int n  = warp_n * 64 + ni * 8 + tg * 2;
            __half2 h01 = __floats2half2_rn(acc[mi][ni][0], acc[mi][ni][1]);
            __half2 h23 = __floats2half2_rn(acc[mi][ni][2], acc[mi][ni][3]);
            *(__half2*)&As[r0 * HS + n]       = h01;
            *(__half2*)&As[(r0 + 8) * HS + n] = h23;
        }
    }
    __syncthreads();
    #pragma unroll
    for (int t = 0; t < 8; t++) {
        int idx = tid + 256 * t;                 // uint4 id over [128][16]
        int r = idx >> 4, c = idx & 15;
        int row = m0 + r;
        if (row < NN)
            ((uint4*)(g_hh + (size_t)row * 128))[c] = *(const uint4*)&As[r * HS + c * 8];
    }
    if (tid < 128) {
        int row = m0 + tid;
        if (row < NN) { g_as[row] = s_as[tid]; g_ad[row] = s_ad[tid]; }
    }
}

// ---------------- 2) CSR build (fork stream — independent of GEMM) ----------------
__global__ void gat_zero_deg()
{
    int i = blockIdx.x * blockDim.x + threadIdx.x;
    if (i < NN) g_deg[i] = 0;
}

__global__ void gat_hist(const int* __restrict__ dst)
{
    int i = blockIdx.x * blockDim.x + threadIdx.x;
    if (i < EE) atomicAdd(&g_deg[dst[i]], 1);
}

__global__ void gat_scan()
{
    __shared__ int s[1024];
    const int tid = threadIdx.x;
    const int C = (NN + 1023) / 1024;
    int start = tid * C;
    int end = start + C; if (end > NN) end = NN;
    if (start > NN) start = NN;

    int sum = 0;
    for (int i = start; i < end; i++) sum += g_deg[i];
    s[tid] = sum;
    for (int o = 1; o < 1024; o <<= 1) {
        __syncthreads();
        int v = (tid >= o) ? s[tid - o] : 0;
        __syncthreads();
        s[tid] += v;
    }
    __syncthreads();
    int run = s[tid] - sum;
    for (int i = start; i < end; i++) {
        g_off[i] = run;
        g_cur[i] = run;
        run += g_deg[i];
    }
    if (tid == 1023) g_off[NN] = s[1023];
}

__global__ void gat_build(const int* __restrict__ src, const int* __restrict__ dst)
{
    int i = blockIdx.x * blockDim.x + threadIdx.x;
    if (i >= EE) return;
    int dv = dst[i];
    int pos = atomicAdd(&g_cur[dv], 1);
    g_ssrc[pos] = src[i];
}

// ---------------- 3) fused softmax + aggregate + epilogue ----------------
// one warp per destination node. p computed inline from CSR (no edge kernel,
// no g_es array). (sidx, p) chunks staged in smem for LDS-broadcast reads.
__global__ void gat_aggregate(const float* __restrict__ x,
                              const float* __restrict__ bias,
                              const float* __restrict__ gamma,
                              const float* __restrict__ beta,
                              float* __restrict__ out)
{
    __shared__ float s_p[8][32];
    __shared__ int   s_i[8][32];

    int w = threadIdx.x >> 5;
    int u = blockIdx.x * (blockDim.x >> 5) + w;
    int lane = threadIdx.x & 31;
    if (u >= NN) return;

    int o   = g_off[u];
    int deg = g_off[u + 1] - o;

    float4 acc = make_float4(0.f, 0.f, 0.f, 0.f);

    if (deg > 0) {
        const float ad_u = g_ad[u];

        // chunk 0 in registers
        int c0 = deg < 32 ? deg : 32;
        int   sidx0 = 0; float p0 = 0.f;
        if (lane < c0) {
            sidx0 = g_ssrc[o + lane];
            float t = g_as[sidx0] + ad_u;
            float e = t > 0.f ? t : NEG_SLOPE * t;
            p0 = __expf(e);
        }
        float sum = p0;
        // remaining chunks (rare; deg>32)
        for (int base = 32; base < deg; base += 32) {
            int j = base + lane;
            if (j < deg) {
                int sv = g_ssrc[o + j];
                float t = g_as[sv] + ad_u;
                float e = t > 0.f ? t : NEG_SLOPE * t;
                sum += __expf(e);
            }
        }
        #pragma unroll
        for (int sh = 16; sh; sh >>= 1) sum += __shfl_xor_sync(0xffffffffu, sum, sh);
        float inv = 1.f / sum;

        // process chunks: stage (sidx, p*inv) in smem, then batched gather
        for (int base = 0; base < deg; base += 32) {
            int cnt = deg - base; if (cnt > 32) cnt = 32;
            if (base == 0) {
                s_i[w][lane] = sidx0;
                s_p[w][lane] = p0 * inv;
            } else {
                int j = base + lane;
                int sv = 0; float pv = 0.f;
                if (j < deg) {
                    sv = g_ssrc[o + j];
                    float t = g_as[sv] + ad_u;
                    float e = t > 0.f ? t : NEG_SLOPE * t;
                    pv = __expf(e) * inv;
                }
                s_i[w][lane] = sv;
                s_p[w][lane] = pv;
            }
            __syncwarp();
            for (int t0 = 0; t0 < cnt; t0 += 4) {
                float p4[4]; int s4[4];
                #pragma unroll
                for (int t = 0; t < 4; t++) {
                    int tt = t0 + t < cnt ? t0 + t : 0;
                    s4[t] = s_i[w][tt];
                    p4[t] = (t0 + t < cnt) ? s_p[w][tt] : 0.f;
                }
                uint2 pk4[4];
                #pragma unroll
                for (int t = 0; t < 4; t++)
                    pk4[t] = ((const uint2*)(g_hh + (size_t)s4[t] * 128))[lane];
                #pragma unroll
                for (int t = 0; t < 4; t++) {
                    float2 f01 = __half22float2(*(const __half2*)&pk4[t].x);
                    float2 f23 = __half22float2(*(const __half2*)&pk4[t].y);
                    acc.x = fmaf(p4[t], f01.x, acc.x);
                    acc.y = fmaf(p4[t], f01.y, acc.y);
                    acc.z = fmaf(p4[t], f23.x, acc.z);
                    acc.w = fmaf(p4[t], f23.y, acc.w);
                }
            }
            __syncwarp();
        }
    }

    // epilogue: bias -> BN(eval) -> ReLU -> residual
    const float inv_s = rsqrtf(1.0f + 1e-5f);
    float4 bv = ((const float4*)bias)[lane];
    float4 gv = ((const float4*)gamma)[lane];
    float4 be = ((const float4*)beta)[lane];
    float4 xv = ((const float4*)(x + (size_t)u * 128))[lane];

    float4 r;
    r.x = xv.x + fmaxf(gv.x * ((acc.x + bv.x) * inv_s) + be.x, 0.f);
    r.y = xv.y + fmaxf(gv.y * ((acc.y + bv.y) * inv_s) + be.y, 0.f);
    r.z = xv.z + fmaxf(gv.z * ((acc.z + bv.z) * inv_s) + be.z, 0.f);
    r.w = xv.w + fmaxf(gv.w * ((acc.w + bv.w) * inv_s) + be.w, 0.f);

    ((float4*)(out + (size_t)u * 128))[lane] = r;
}

// ---------------- stream/event handles (created pre-baseline, once) ----------------
struct StreamInit {
    cudaStream_t s;
    cudaEvent_t  eFork, eJoin;
    StreamInit() {
        cudaStreamCreateWithFlags(&s, cudaStreamNonBlocking);
        cudaEventCreateWithFlags(&eFork, cudaEventDisableTiming);
        cudaEventCreateWithFlags(&eJoin, cudaEventDisableTiming);
    }
};
static StreamInit g_si;

// ---------------- launch ----------------
extern "C" void kernel_launch(void* const* d_in, const int* in_sizes, int n_in,
                              void* d_out, int out_size)
{
    const float* x        = (const float*)d_in[0];
    const int*   edge     = (const int*)d_in[1];
    const float* W        = (const float*)d_in[2];
    const float* att_src  = (const float*)d_in[3];
    const float* att_dst  = (const float*)d_in[4];
    const float* bias     = (const float*)d_in[5];
    const float* gamma    = (const float*)d_in[6];
    const float* beta     = (const float*)d_in[7];
    float* out            = (float*)d_out;

    const int* src = edge;
    const int* dst = edge + EE;

    static const size_t GEMM_SMEM = (size_t)(2 * 128 * HS) * sizeof(__half)
                                  + 2 * 128 * sizeof(float);
    cudaFuncSetAttribute(gat_gemm_hmma, cudaFuncAttributeMaxDynamicSharedMemorySize,
                         (int)GEMM_SMEM);

    // fork: CSR structure build (depends only on edge_index), overlapped with GEMM
    cudaEventRecord(g_si.eFork, 0);
    cudaStreamWaitEvent(g_si.s, g_si.eFork, 0);
    gat_zero_deg<<<(NN + 255) / 256, 256, 0, g_si.s>>>();
    gat_hist<<<(EE + 255) / 256, 256, 0, g_si.s>>>(dst);
    gat_scan<<<1, 1024, 0, g_si.s>>>();
    gat_build<<<(EE + 255) / 256, 256, 0, g_si.s>>>(src, dst);
    cudaEventRecord(g_si.eJoin, g_si.s);

    gat_gemm_hmma<<<(NN + 127) / 128, 256, GEMM_SMEM>>>(x, W, att_src, att_dst);

    // join: aggregate needs a_s/a_d/h (gemm) + CSR (build)
    cudaStreamWaitEvent(0, g_si.eJoin, 0);
    gat_aggregate<<<(NN + 7) / 8, 256>>>(x, bias, gamma, beta, out);
}